// round 4
// baseline (speedup 1.0000x reference)
#include <cuda_runtime.h>

// FFT_19490561589800: batch of 16384 x 1024-point FFT of real input.
// Output: [real plane (16384x1024), imag plane (16384x1024)] fp32.
//
// Algorithm: four-step FFT, 1024 = 32 x 32.
//   n = 32*n1 + n2, k = k1 + 32*k2
//   X[k1+32k2] = sum_n2 W32^{n2 k2} * W1024^{n2 k1} * sum_n1 x[32n1+n2] W32^{n1 k1}
// One warp handles TWO real rows packed as one complex FFT (Hermitian trick):
//   z = a + i b;  X_a[k] = (Z[k]+conj(Z[N-k]))/2;  X_b[k] = (Z[k]-conj(Z[N-k]))/(2i)
// All row-local data exchange is warp-private shared memory (+__syncwarp only).

static constexpr int N = 1024;

// 5-bit bit reversal, usable from both host and device code; folds to an
// immediate at every (fully unrolled) call site.
__device__ __host__ constexpr int br5(int i){
    return ((i & 1) << 4) | ((i & 2) << 2) | (i & 4) | ((i & 8) >> 2) | ((i & 16) >> 4);
}

__device__ __forceinline__ float2 cmulf(float2 a, float2 b){
    return make_float2(fmaf(a.x, b.x, -(a.y * b.y)),
                       fmaf(a.x, b.y,  (a.y * b.x)));
}

// One DIF radix-2 stage of an in-register 32-point FFT.
// Twiddles W_32^j = C[j] + i*S[j]  (S = -sin) appear as immediates after unroll.
template<int LEN>
__device__ __forceinline__ void fft32_stage(float2* v){
    constexpr int HALF = LEN / 2;
    constexpr int TS   = 32 / LEN;
    constexpr float C[16] = {
        1.0f,                 0.98078528040323044f, 0.92387953251128674f, 0.83146961230254524f,
        0.70710678118654752f, 0.55557023301960222f, 0.38268343236508977f, 0.19509032201612825f,
        0.0f,                -0.19509032201612825f,-0.38268343236508977f,-0.55557023301960222f,
       -0.70710678118654752f,-0.83146961230254524f,-0.92387953251128674f,-0.98078528040323044f};
    constexpr float S[16] = {
        0.0f,                -0.19509032201612825f,-0.38268343236508977f,-0.55557023301960222f,
       -0.70710678118654752f,-0.83146961230254524f,-0.92387953251128674f,-0.98078528040323044f,
       -1.0f,                -0.98078528040323044f,-0.92387953251128674f,-0.83146961230254524f,
       -0.70710678118654752f,-0.55557023301960222f,-0.38268343236508977f,-0.19509032201612825f};
#pragma unroll
    for (int base = 0; base < 32; base += LEN){
#pragma unroll
        for (int j = 0; j < HALF; j++){
            float2 a = v[base + j];
            float2 b = v[base + j + HALF];
            float2 s = make_float2(a.x + b.x, a.y + b.y);
            float2 d = make_float2(a.x - b.x, a.y - b.y);
            const int tj = j * TS;   // compile-time after unroll
            float2 r;
            if      (tj == 0) r = d;
            else if (tj == 8) r = make_float2(d.y, -d.x);             // * (-i)
            else              r = make_float2(d.x*C[tj] - d.y*S[tj],
                                              d.x*S[tj] + d.y*C[tj]);
            v[base + j]        = s;
            v[base + j + HALF] = r;
        }
    }
}

// In-register 32-point FFT, natural-order input, bit-reversed output:
// after call, v[i] = X[br5(i)]
__device__ __forceinline__ void fft32(float2* v){
    fft32_stage<32>(v);
    fft32_stage<16>(v);
    fft32_stage<8>(v);
    fft32_stage<4>(v);
    fft32_stage<2>(v);
}

#define PAIRS_PER_BLOCK 4
#define THREADS 128

__global__ void __launch_bounds__(THREADS, 4)
fft_kernel(const float* __restrict__ x,
           const float* __restrict__ twr,   // tw_real_3: cos(2*pi*j/1024), j<512
           const float* __restrict__ twi,   // tw_imag_3: -sin(2*pi*j/1024)
           float* __restrict__ out,
           int n_rows)
{
    // per-warp transpose buffers: 32x32 with pad 33 (conflict-free both phases)
    __shared__ float s_re[PAIRS_PER_BLOCK][33 * 32];
    __shared__ float s_im[PAIRS_PER_BLOCK][33 * 32];

    const int t = threadIdx.x & 31;    // lane
    const int w = threadIdx.x >> 5;    // warp in block = pair in block
    const int pair = blockIdx.x * PAIRS_PER_BLOCK + w;
    const int rowa = pair * 2;
    const int rowb = rowa + 1;
    if (rowb > n_rows) return;

    const size_t IMOFF = (size_t)n_rows * N;   // offset of imag plane in out

    const float* xa = x + (size_t)rowa * N;
    const float* xb = x + (size_t)rowb * N;
    float* sre = s_re[w];
    float* sim = s_im[w];

    // ---- load: z[n] = xa[n] + i*xb[n]; thread t owns n2 = t, n = 32*n1 + t ----
    float2 v[32];
#pragma unroll
    for (int n1 = 0; n1 < 32; n1++){
        v[n1].x = xa[32 * n1 + t];
        v[n1].y = xb[32 * n1 + t];
    }

    // ---- stage A: 32-pt FFT over n1 ----
    fft32(v);                       // v[i] = A[br5(i)]

    // ---- inter-stage twiddle: A[k1] *= W_1024^{t*k1}, via recurrence ----
    {
        float2 base = make_float2(twr[t], twi[t]);   // W_1024^t
        float2 cur  = base;
#pragma unroll
        for (int k1 = 1; k1 < 32; k1++){
            const int i = br5(k1);                   // v[i] holds A[k1]
            v[i] = cmulf(v[i], cur);
            cur = cmulf(cur, base);
        }
    }

    // ---- transpose via shared: (k1, n2=t) -> thread t becomes k1 ----
#pragma unroll
    for (int i = 0; i < 32; i++){
        const int k1 = br5(i);
        sre[k1 * 33 + t] = v[i].x;
        sim[k1 * 33 + t] = v[i].y;
    }
    __syncwarp();
#pragma unroll
    for (int n2 = 0; n2 < 32; n2++){
        v[n2].x = sre[t * 33 + n2];
        v[n2].y = sim[t * 33 + n2];
    }
    __syncwarp();   // WAR: everyone done reading before buffer reuse below

    // ---- stage B: 32-pt FFT over n2 ----
    fft32(v);                       // v[i] = Z[t + 32*br5(i)]

    // ---- store Z to shared in natural order k = t + 32*k2 ----
#pragma unroll
    for (int i = 0; i < 32; i++){
        const int k2 = br5(i);
        sre[t + 32 * k2] = v[i].x;
        sim[t + 32 * k2] = v[i].y;
    }
    __syncwarp();

    // ---- Hermitian unpack: two real-row spectra from one complex FFT ----
    float* oar = out + (size_t)rowa * N;
    float* oai = oar + IMOFF;
    float* obr = out + (size_t)rowb * N;
    float* obi = obr + IMOFF;
#pragma unroll
    for (int k2 = 0; k2 < 32; k2++){
        const int k = t + 32 * k2;
        const int m = (N - k) & (N - 1);
        const float zr = sre[k], zi = sim[k];
        const float wr = sre[m], wi = sim[m];
        oar[k] = 0.5f * (zr + wr);
        oai[k] = 0.5f * (zi - wi);
        obr[k] = 0.5f * (zi + wi);
        obi[k] = 0.5f * (wr - zr);
    }
}

extern "C" void kernel_launch(void* const* d_in, const int* in_sizes, int n_in,
                              void* d_out, int out_size)
{
    const float* x   = (const float*)d_in[0];
    const float* twr = (const float*)d_in[10];   // tw_real_3 (512: W_1024^j)
    const float* twi = (const float*)d_in[11];   // tw_imag_3
    float* out = (float*)d_out;

    const int n_rows = in_sizes[0] / N;          // 16384
    const int pairs  = n_rows / 2;               // 8192
    const int blocks = (pairs + PAIRS_PER_BLOCK - 1) / PAIRS_PER_BLOCK;  // 2048

    fft_kernel<<<blocks, THREADS>>>(x, twr, twi, out, n_rows);
}